// round 14
// baseline (speedup 1.0000x reference)
#include <cuda_runtime.h>
#include <cstdint>

#define SLEN 2048
#define BATCH 64
#define HID 512
#define G4 2048
#define NBLK 128
#define TPB 256

// ---------------- scratch (device globals) ----------------
static __device__ float g_xp[(size_t)SLEN * G4 * BATCH];   // [s][g][b], 1 GiB
static __device__ float g_hT[2][HID * BATCH];              // transposed h [j][b], ping-pong
static __device__ unsigned g_leaf[8];                      // monotonic arrival counters

// ---------------- packed f32x2 helpers ----------------
__device__ __forceinline__ uint64_t f2_pack(float x, float y) {
    uint64_t r; uint32_t xu = __float_as_uint(x), yu = __float_as_uint(y);
    asm("mov.b64 %0, {%1, %2};" : "=l"(r) : "r"(xu), "r"(yu));
    return r;
}
__device__ __forceinline__ uint64_t f2_dup(float x) {
    uint64_t r; uint32_t xu = __float_as_uint(x);
    asm("mov.b64 %0, {%1, %1};" : "=l"(r) : "r"(xu));
    return r;
}
__device__ __forceinline__ void f2_fma(uint64_t& d, uint64_t a, uint64_t b) {
    asm("fma.rn.f32x2 %0, %1, %2, %0;" : "+l"(d) : "l"(a), "l"(b));
}
__device__ __forceinline__ void f2_add(uint64_t& d, uint64_t a) {
    asm("add.rn.f32x2 %0, %1, %0;" : "+l"(d) : "l"(a));
}
__device__ __forceinline__ float2 f2_unpack(uint64_t v) {
    uint32_t lo, hi;
    asm("mov.b64 {%0, %1}, %2;" : "=r"(lo), "=r"(hi) : "l"(v));
    return make_float2(__uint_as_float(lo), __uint_as_float(hi));
}

// ---------------- kernel 1: x_proj GEMM (+ folded h_prev transpose + leaf reset) ----------------
__global__ __launch_bounds__(256, 2) void xproj_gemm_kernel(
    const float* __restrict__ A,    // (131072, 512)
    const float* __restrict__ W,    // (2048, 512)
    const float* __restrict__ bi,
    const float* __restrict__ bh,
    const float* __restrict__ h_prev)
{
    __shared__ float Ash[16][132];
    __shared__ float Bsh[16][132];

    const int tid = threadIdx.x;

    // folded init: transpose h_prev -> g_hT[1]; zero leaf counters (replay-safe)
    if (blockIdx.y == 0 && blockIdx.x < 128) {
        int idx = blockIdx.x * 256 + tid;    // 0..32767
        int j = idx >> 6, b = idx & 63;
        g_hT[1][idx] = h_prev[(size_t)b * HID + j];
        if (blockIdx.x == 0 && tid < 8) g_leaf[tid] = 0u;
    }

    const int tx = tid & 15;
    const int ty = tid >> 4;
    const int m0 = blockIdx.x * 128;
    const int g0 = blockIdx.y * 128;

    uint64_t acc[8][4];
#pragma unroll
    for (int g = 0; g < 8; ++g)
#pragma unroll
        for (int p = 0; p < 4; ++p) acc[g][p] = 0ull;

    for (int kt = 0; kt < 32; ++kt) {
        const int k0 = kt * 16;
#pragma unroll
        for (int i = 0; i < 2; ++i) {
            int idx = tid + i * 256;
            int r = idx >> 2, c4 = idx & 3;
            float4 va = *(const float4*)(A + (size_t)(m0 + r) * 512 + k0 + c4 * 4);
            Ash[c4 * 4 + 0][r] = va.x; Ash[c4 * 4 + 1][r] = va.y;
            Ash[c4 * 4 + 2][r] = va.z; Ash[c4 * 4 + 3][r] = va.w;
            float4 vb = *(const float4*)(W + (size_t)(g0 + r) * 512 + k0 + c4 * 4);
            Bsh[c4 * 4 + 0][r] = vb.x; Bsh[c4 * 4 + 1][r] = vb.y;
            Bsh[c4 * 4 + 2][r] = vb.z; Bsh[c4 * 4 + 3][r] = vb.w;
        }
        __syncthreads();
#pragma unroll
        for (int kk = 0; kk < 16; ++kk) {
            uint64_t a[4];
            const uint64_t* ap = (const uint64_t*)&Ash[kk][ty * 8];
            a[0] = ap[0]; a[1] = ap[1]; a[2] = ap[2]; a[3] = ap[3];
            float4 q0 = *(const float4*)&Bsh[kk][tx * 8];
            float4 q1 = *(const float4*)&Bsh[kk][tx * 8 + 4];
            float bv[8] = {q0.x, q0.y, q0.z, q0.w, q1.x, q1.y, q1.z, q1.w};
#pragma unroll
            for (int g = 0; g < 8; ++g) {
                uint64_t bd = f2_dup(bv[g]);
                f2_fma(acc[g][0], a[0], bd);
                f2_fma(acc[g][1], a[1], bd);
                f2_fma(acc[g][2], a[2], bd);
                f2_fma(acc[g][3], a[3], bd);
            }
        }
        __syncthreads();
    }

    const int s  = blockIdx.x * 2 + (ty >> 3);
    const int b0 = (ty & 7) * 8;
#pragma unroll
    for (int g = 0; g < 8; ++g) {
        int gg = g0 + tx * 8 + g;
        float bsum = __ldg(bi + gg) + __ldg(bh + gg);
        float2 p0 = f2_unpack(acc[g][0]);
        float2 p1 = f2_unpack(acc[g][1]);
        float2 p2 = f2_unpack(acc[g][2]);
        float2 p3 = f2_unpack(acc[g][3]);
        float4 v0 = make_float4(p0.x + bsum, p0.y + bsum, p1.x + bsum, p1.y + bsum);
        float4 v1 = make_float4(p2.x + bsum, p2.y + bsum, p3.x + bsum, p3.y + bsum);
        float* dst = g_xp + ((size_t)s * G4 + gg) * 64 + b0;
        *(float4*)dst = v0;
        *(float4*)(dst + 4) = v1;
    }
}

// ---------------- kernel 2: persistent recurrent LSTM ----------------
// R13 + distributed leaf-counter sync:
//  - 8 monotonic leaf counters; leaf l counts arrivals of blocks ug in [16l,16l+16)
//  - warp w consumes h rows 64w..64w+63 produced exactly by leaf w's blocks ->
//    warp w's lane0 polls leaf[w] >= 16*s (ld.acquire), __syncwarp, stage. No
//    block-wide loop-top barrier, no root/epoch hops, no nanosleep, no resets.
//  - arrive = ONE fire-and-forget red.add.release (after post-act syncthreads).
// Intra-block hazards (partials alias staging, hbuf WAR) stay covered by the
// 3 in-step __syncthreads; own-block reduce completes before its loop-top polls.
__global__ __launch_bounds__(TPB, 1) void lstm_rec_kernel(
    const float* __restrict__ c_prev,
    const float* __restrict__ Whh,
    float* __restrict__ out)
{
    extern __shared__ char smp[];
    uint64_t* W2u  = (uint64_t*)smp;              // [512 k][8 rp] row-pairs, 32 KB
    char*     hreg = smp + 32768;                 // staging 128 KB (per-warp 16 KB); partials alias
    float*    zb   = (float*)(smp + 32768 + 131072);  // [16 rows][64 b], 4 KB
    float*    hbuf = (float*)(smp + 32768 + 131072 + 4096);  // [64 b][4 u], 1 KB

    const int tid  = threadIdx.x;
    const int w    = tid >> 5;       // 8 warps
    const int lane = tid & 31;
    const int rq   = lane >> 4;      // row-quad 0/1
    const int bq   = lane & 15;      // b-quad 0..15
    const int u    = tid >> 6;       // activation: unit 0..3
    const int bb   = tid & 63;       // activation: batch
    const int ug   = blockIdx.x;
    const int j    = ug * 4 + u;

    // --- W setup: W2u[k*8+rp] = (Whh[row(2rp)][k], Whh[row(2rp+1)][k]); row r = g*4+u ---
    for (int idx = tid; idx < 512 * 8; idx += TPB) {
        int k = idx >> 3, rp = idx & 7;
        int r0 = 2 * rp, r1 = 2 * rp + 1;
        int row0 = (r0 >> 2) * HID + ug * 4 + (r0 & 3);
        int row1 = (r1 >> 2) * HID + ug * 4 + (r1 & 3);
        W2u[idx] = f2_pack(Whh[(size_t)row0 * HID + k], Whh[(size_t)row1 * HID + k]);
    }

    float c = c_prev[(size_t)bb * HID + j];
    float xi = g_xp[(size_t)(0 * HID + j) * 64 + bb];
    float xf = g_xp[(size_t)(1 * HID + j) * 64 + bb];
    float xg = g_xp[(size_t)(2 * HID + j) * 64 + bb];
    float xo = g_xp[(size_t)(3 * HID + j) * 64 + bb];

    float* hst = (float*)(hreg + w * 16384);      // warp slice [64 k local][64 b]
    uint32_t hst_s = (uint32_t)__cvta_generic_to_shared(hst);
    const uint64_t* W2w = W2u + (size_t)w * 64 * 8;
    const unsigned* leafp = &g_leaf[w];

    __syncthreads();   // W2u ready

    for (int s = 0; s < SLEN; ++s) {
        // --- distributed wait: warp w polls ONLY its producers' leaf counter ---
        if (s > 0) {
            if (lane == 0) {
                const unsigned tgt = (unsigned)(16 * s);
                unsigned cur;
                do {
                    asm volatile("ld.acquire.gpu.global.u32 %0, [%1];"
                                 : "=r"(cur) : "l"(leafp) : "memory");
                } while ((int)(cur - tgt) < 0);
            }
            __syncwarp();
        }

        // --- stage warp's 16KB h slice: 4 chunks of 16 k ---
        const float* hsrc = g_hT[(s + 1) & 1] + (size_t)w * 64 * 64;
#pragma unroll
        for (int ch = 0; ch < 4; ++ch) {
#pragma unroll
            for (int i = 0; i < 8; ++i) {
                int flat = ch * 256 + i * 32 + lane;   // float4 index
                asm volatile("cp.async.cg.shared.global [%0], [%1], 16;"
                             :: "r"(hst_s + flat * 16), "l"(hsrc + flat * 4));
            }
            asm volatile("cp.async.commit_group;");
        }

        uint64_t acc[4][4];    // [row-pair local][b local]
#pragma unroll
        for (int i = 0; i < 4; ++i)
#pragma unroll
            for (int p = 0; p < 4; ++p) acc[i][p] = 0ull;

        const float zxi = xi, zxf = xf, zxg = xg, zxo = xo;
        if (s + 1 < SLEN) {    // prefetch next xp under compute (no barrier dependency)
            size_t nb = (size_t)(s + 1) * G4 * 64;
            xi = g_xp[nb + (size_t)(0 * HID + j) * 64 + bb];
            xf = g_xp[nb + (size_t)(1 * HID + j) * 64 + bb];
            xg = g_xp[nb + (size_t)(2 * HID + j) * 64 + bb];
            xo = g_xp[nb + (size_t)(3 * HID + j) * 64 + bb];
        }

#pragma unroll
        for (int ch = 0; ch < 4; ++ch) {
            switch (ch) {
                case 0: asm volatile("cp.async.wait_group 3;"); break;
                case 1: asm volatile("cp.async.wait_group 2;"); break;
                case 2: asm volatile("cp.async.wait_group 1;"); break;
                default: asm volatile("cp.async.wait_group 0;");
            }
            __syncwarp();
#pragma unroll
            for (int kk = 0; kk < 16; ++kk) {
                const int k = ch * 16 + kk;            // local k
                float4 hq = *(const float4*)(hst + k * 64 + bq * 4);
                uint64_t h0 = f2_dup(hq.x), h1 = f2_dup(hq.y);
                uint64_t h2 = f2_dup(hq.z), h3 = f2_dup(hq.w);
                const uint64_t* Wk = W2w + (size_t)k * 8 + rq * 4;
                ulonglong2 wA = *(const ulonglong2*)Wk;
                ulonglong2 wB = *(const ulonglong2*)(Wk + 2);
                f2_fma(acc[0][0], h0, wA.x); f2_fma(acc[0][1], h1, wA.x);
                f2_fma(acc[0][2], h2, wA.x); f2_fma(acc[0][3], h3, wA.x);
                f2_fma(acc[1][0], h0, wA.y); f2_fma(acc[1][1], h1, wA.y);
                f2_fma(acc[1][2], h2, wA.y); f2_fma(acc[1][3], h3, wA.y);
                f2_fma(acc[2][0], h0, wB.x); f2_fma(acc[2][1], h1, wB.x);
                f2_fma(acc[2][2], h2, wB.x); f2_fma(acc[2][3], h3, wB.x);
                f2_fma(acc[3][0], h0, wB.y); f2_fma(acc[3][1], h1, wB.y);
                f2_fma(acc[3][2], h2, wB.y); f2_fma(acc[3][3], h3, wB.y);
            }
        }

        // --- partials into per-warp region (aliases staging, all consumed) ---
        __syncthreads();
        {
            uint64_t* part = (uint64_t*)hreg + (size_t)w * 512;   // [8 rp][64 b] pairs
#pragma unroll
            for (int rpl = 0; rpl < 4; ++rpl) {
#pragma unroll
                for (int bi = 0; bi < 4; bi += 2) {
                    int p = (rq * 4 + rpl) * 64 + bq * 4 + bi;
                    *(ulonglong2*)(part + p) =
                        make_ulonglong2(acc[rpl][bi], acc[rpl][bi + 1]);
                }
            }
        }
        __syncthreads();

        // --- reduce over 8 warps: thread t owns pairs 2t, 2t+1 ---
        {
            const uint64_t* part = (const uint64_t*)hreg;
            ulonglong2 v0 = *(const ulonglong2*)(part + 2 * tid);
            uint64_t e = v0.x, o = v0.y;
#pragma unroll
            for (int ww = 1; ww < 8; ++ww) {
                ulonglong2 v = *(const ulonglong2*)(part + ww * 512 + 2 * tid);
                f2_add(e, v.x);
                f2_add(o, v.y);
            }
            int rp = tid >> 5;
            int b  = (2 * tid) & 63;
            float2 E = f2_unpack(e), O = f2_unpack(o);
            *(float2*)&zb[(2 * rp) * 64 + b]     = make_float2(E.x, O.x);
            *(float2*)&zb[(2 * rp + 1) * 64 + b] = make_float2(E.y, O.y);
        }
        __syncthreads();

        // --- activations: thread (u, bb) ---
        {
            float z_i = zb[(0 * 4 + u) * 64 + bb] + zxi;
            float z_f = zb[(1 * 4 + u) * 64 + bb] + zxf;
            float z_g = zb[(2 * 4 + u) * 64 + bb] + zxg;
            float z_o = zb[(3 * 4 + u) * 64 + bb] + zxo;
            float ig = 1.f / (1.f + __expf(-z_i));
            float fg = 1.f / (1.f + __expf(-z_f));
            float gt = tanhf(z_g);
            float og = 1.f / (1.f + __expf(-z_o));
            c = fg * c + ig * gt;
            float h = og * tanhf(c);

            g_hT[s & 1][j * 64 + bb] = h;     // coalesced (bb consecutive)
            hbuf[bb * 4 + u] = h;

            if (s == SLEN - 1) {
                const size_t SBH = (size_t)SLEN * BATCH * HID;
                size_t o2 = (size_t)bb * HID + j;
                out[SBH + o2] = h;                          // h_f
                out[SBH + (size_t)BATCH * HID + o2] = c;    // c_f
            }
        }
        __syncthreads();   // h stores block-wide complete -> release below covers them

        // --- arrive: ONE fire-and-forget release add; no spin here ---
        if (tid == 0) {
            asm volatile("red.add.release.gpu.global.u32 [%0], %1;"
                         :: "l"(&g_leaf[ug >> 4]), "r"(1u) : "memory");
        }

        // out stores: coalesced float4, off the publish path
        if (tid < 64) {
            float4 hv = *(const float4*)(hbuf + tid * 4);
            *(float4*)(out + ((size_t)s * BATCH + tid) * HID + ug * 4) = hv;
        }
    }
}

// ---------------- launch ----------------
extern "C" void kernel_launch(void* const* d_in, const int* in_sizes, int n_in,
                              void* d_out, int out_size) {
    (void)in_sizes; (void)n_in; (void)out_size;
    const float* input  = (const float*)d_in[0];  // (2048, 64, 512)
    const float* h_prev = (const float*)d_in[1];  // (64, 512)
    const float* c_prev = (const float*)d_in[2];  // (64, 512)
    const float* w_ih   = (const float*)d_in[3];  // (2048, 512)
    const float* w_hh   = (const float*)d_in[4];  // (2048, 512)
    const float* b_ih   = (const float*)d_in[5];  // (2048,)
    const float* b_hh   = (const float*)d_in[6];  // (2048,)
    float* out = (float*)d_out;

    cudaFuncSetAttribute(lstm_rec_kernel,
                         cudaFuncAttributeMaxDynamicSharedMemorySize, 172032);

    // 2 launches per call (init folded into GEMM) -> ncu -s 5 -c 1 lands on rec
    dim3 g1(131072 / 128, 2048 / 128);   // (1024, 16)
    xproj_gemm_kernel<<<g1, 256>>>(input, w_ih, b_ih, b_hh, h_prev);

    lstm_rec_kernel<<<NBLK, TPB, 172032>>>(c_prev, w_hh, out);
}

// round 15
// speedup vs baseline: 1.3277x; 1.3277x over previous
#include <cuda_runtime.h>
#include <cstdint>

#define SLEN 2048
#define BATCH 64
#define HID 512
#define G4 2048
#define NBG 4            // batch groups (independent recurrences)
#define NUG 32           // unit groups
#define NBLK (NBG*NUG)   // 128
#define UPB 16           // units per block
#define BPB 16           // batches per block
#define TPB 256

// ---------------- scratch (device globals) ----------------
static __device__ float g_xp[(size_t)SLEN * G4 * BATCH];   // [s][g][b], 1 GiB
static __device__ float g_h[2][NBG][HID * BPB];            // ping-pong h, [bg][j*16+b]
static __device__ unsigned g_cnt[NBG];                     // monotonic arrival counters

// ---------------- packed f32x2 helpers ----------------
__device__ __forceinline__ uint64_t f2_pack(float x, float y) {
    uint64_t r; uint32_t xu = __float_as_uint(x), yu = __float_as_uint(y);
    asm("mov.b64 %0, {%1, %2};" : "=l"(r) : "r"(xu), "r"(yu));
    return r;
}
__device__ __forceinline__ uint64_t f2_dup(float x) {
    uint64_t r; uint32_t xu = __float_as_uint(x);
    asm("mov.b64 %0, {%1, %1};" : "=l"(r) : "r"(xu));
    return r;
}
__device__ __forceinline__ void f2_fma(uint64_t& d, uint64_t a, uint64_t b) {
    asm("fma.rn.f32x2 %0, %1, %2, %0;" : "+l"(d) : "l"(a), "l"(b));
}
__device__ __forceinline__ void f2_add(uint64_t& d, uint64_t a) {
    asm("add.rn.f32x2 %0, %1, %0;" : "+l"(d) : "l"(a));
}
__device__ __forceinline__ float2 f2_unpack(uint64_t v) {
    uint32_t lo, hi;
    asm("mov.b64 {%0, %1}, %2;" : "=r"(lo), "=r"(hi) : "l"(v));
    return make_float2(__uint_as_float(lo), __uint_as_float(hi));
}

// ---------------- kernel 1: x_proj GEMM (+ folded init) ----------------
__global__ __launch_bounds__(256, 2) void xproj_gemm_kernel(
    const float* __restrict__ A,    // (131072, 512)
    const float* __restrict__ W,    // (2048, 512)
    const float* __restrict__ bi,
    const float* __restrict__ bh,
    const float* __restrict__ h_prev)
{
    __shared__ float Ash[16][132];
    __shared__ float Bsh[16][132];

    const int tid = threadIdx.x;

    // folded init: h_prev -> g_h[1][bg][j*16+b_local]; zero group counters
    if (blockIdx.y == 0 && blockIdx.x < 128) {
        int idx = blockIdx.x * 256 + tid;    // 0..32767
        int j = idx >> 6, b = idx & 63;
        g_h[1][b >> 4][j * BPB + (b & 15)] = h_prev[(size_t)b * HID + j];
        if (blockIdx.x == 0 && tid < NBG) g_cnt[tid] = 0u;
    }

    const int tx = tid & 15;
    const int ty = tid >> 4;
    const int m0 = blockIdx.x * 128;
    const int g0 = blockIdx.y * 128;

    uint64_t acc[8][4];
#pragma unroll
    for (int g = 0; g < 8; ++g)
#pragma unroll
        for (int p = 0; p < 4; ++p) acc[g][p] = 0ull;

    for (int kt = 0; kt < 32; ++kt) {
        const int k0 = kt * 16;
#pragma unroll
        for (int i = 0; i < 2; ++i) {
            int idx = tid + i * 256;
            int r = idx >> 2, c4 = idx & 3;
            float4 va = *(const float4*)(A + (size_t)(m0 + r) * 512 + k0 + c4 * 4);
            Ash[c4 * 4 + 0][r] = va.x; Ash[c4 * 4 + 1][r] = va.y;
            Ash[c4 * 4 + 2][r] = va.z; Ash[c4 * 4 + 3][r] = va.w;
            float4 vb = *(const float4*)(W + (size_t)(g0 + r) * 512 + k0 + c4 * 4);
            Bsh[c4 * 4 + 0][r] = vb.x; Bsh[c4 * 4 + 1][r] = vb.y;
            Bsh[c4 * 4 + 2][r] = vb.z; Bsh[c4 * 4 + 3][r] = vb.w;
        }
        __syncthreads();
#pragma unroll
        for (int kk = 0; kk < 16; ++kk) {
            uint64_t a[4];
            const uint64_t* ap = (const uint64_t*)&Ash[kk][ty * 8];
            a[0] = ap[0]; a[1] = ap[1]; a[2] = ap[2]; a[3] = ap[3];
            float4 q0 = *(const float4*)&Bsh[kk][tx * 8];
            float4 q1 = *(const float4*)&Bsh[kk][tx * 8 + 4];
            float bv[8] = {q0.x, q0.y, q0.z, q0.w, q1.x, q1.y, q1.z, q1.w};
#pragma unroll
            for (int g = 0; g < 8; ++g) {
                uint64_t bd = f2_dup(bv[g]);
                f2_fma(acc[g][0], a[0], bd);
                f2_fma(acc[g][1], a[1], bd);
                f2_fma(acc[g][2], a[2], bd);
                f2_fma(acc[g][3], a[3], bd);
            }
        }
        __syncthreads();
    }

    const int s  = blockIdx.x * 2 + (ty >> 3);
    const int b0 = (ty & 7) * 8;
#pragma unroll
    for (int g = 0; g < 8; ++g) {
        int gg = g0 + tx * 8 + g;
        float bsum = __ldg(bi + gg) + __ldg(bh + gg);
        float2 p0 = f2_unpack(acc[g][0]);
        float2 p1 = f2_unpack(acc[g][1]);
        float2 p2 = f2_unpack(acc[g][2]);
        float2 p3 = f2_unpack(acc[g][3]);
        float4 v0 = make_float4(p0.x + bsum, p0.y + bsum, p1.x + bsum, p1.y + bsum);
        float4 v1 = make_float4(p2.x + bsum, p2.y + bsum, p3.x + bsum, p3.y + bsum);
        float* dst = g_xp + ((size_t)s * G4 + gg) * 64 + b0;
        *(float4*)dst = v0;
        *(float4*)(dst + 4) = v1;
    }
}

// ---------------- kernel 2: persistent recurrent LSTM ----------------
// Batch-split: 128 blocks = (bg in 4) x (ug in 32); block = 16 units x 16 batches
// (64 gate rows). h traffic per block per step: 32KB (vs 128KB in R13) ->
// chip 4MB/step (~650 cyc LTS) instead of 16MB (~2600 cyc).
// Sync (R13 discipline, per group): arrive = ONE red.add.release on g_cnt[bg];
// wait = tid0 polls cnt >= 32*(s+1). 32 pollers/line, 4 disjoint lines.
// Compute: 8 warps x 64-k slices; lane=(rg in 8)x(bh in 4); 16 f32x2 accs.
__global__ __launch_bounds__(TPB, 1) void lstm_rec_kernel(
    const float* __restrict__ c_prev,
    const float* __restrict__ Whh,
    float* __restrict__ out)
{
    extern __shared__ char smp[];
    uint64_t* W2u  = (uint64_t*)smp;              // [512 k][32 rp] row pairs, 128 KB
    char*     hreg = smp + 131072;                // staging 32 KB (per-warp 4 KB); partials alias
    float*    zb   = (float*)(smp + 131072 + 32768);          // [64 rows][16 b], 4 KB
    float*    hbuf = (float*)(smp + 131072 + 32768 + 4096);   // [16 b][16 u], 1 KB

    const int tid  = threadIdx.x;
    const int w    = tid >> 5;       // 8 warps, k-slice [64w, 64w+64)
    const int lane = tid & 31;
    const int rg   = lane >> 2;      // row-pair quad 0..7 (rp = rg*4 .. rg*4+3)
    const int bh   = lane & 3;       // b-quad 0..3
    const int u    = tid >> 4;       // activation: unit 0..15
    const int bb   = tid & 15;       // activation: batch local
    const int bg   = blockIdx.x & 3;
    const int ug   = blockIdx.x >> 2;
    const int j    = ug * UPB + u;
    const int gb   = bg * BPB + bb;  // global batch

    // --- W setup: W2u[k*32+rp] = (Whh[row 2rp][k], Whh[row 2rp+1][k]);
    //     local row r (0..63): gate = r>>4, unit = r&15 ---
    for (int idx = tid; idx < 512 * 32; idx += TPB) {
        int k = idx >> 5, rp = idx & 31;
        int r0 = 2 * rp, r1 = 2 * rp + 1;
        int row0 = (r0 >> 4) * HID + ug * UPB + (r0 & 15);
        int row1 = (r1 >> 4) * HID + ug * UPB + (r1 & 15);
        W2u[idx] = f2_pack(Whh[(size_t)row0 * HID + k], Whh[(size_t)row1 * HID + k]);
    }

    float c  = c_prev[(size_t)gb * HID + j];
    float xi = g_xp[(size_t)(0 * HID + j) * 64 + gb];
    float xf = g_xp[(size_t)(1 * HID + j) * 64 + gb];
    float xg = g_xp[(size_t)(2 * HID + j) * 64 + gb];
    float xo = g_xp[(size_t)(3 * HID + j) * 64 + gb];

    float* hst = (float*)(hreg + w * 4096);       // warp slice [64 k local][16 b]
    uint32_t hst_s = (uint32_t)__cvta_generic_to_shared(hst);
    const uint64_t* W2w = W2u + (size_t)w * 64 * 32;   // warp's global-k W base
    const unsigned* cntp = &g_cnt[bg];

    __syncthreads();   // W2u ready

    for (int s = 0; s < SLEN; ++s) {
        // --- stage warp's 4KB h slice (h[s-1] readiness ensured by prev-iter spin) ---
        const float* hsrc = &g_h[(s + 1) & 1][bg][(size_t)w * 64 * BPB];
#pragma unroll
        for (int i = 0; i < 8; ++i) {
            int flat = i * 32 + lane;              // float4 index, 256 per warp
            asm volatile("cp.async.cg.shared.global [%0], [%1], 16;"
                         :: "r"(hst_s + flat * 16), "l"(hsrc + flat * 4));
        }
        asm volatile("cp.async.commit_group;");

        uint64_t acc[4][4];    // [rpl][bi]
#pragma unroll
        for (int i = 0; i < 4; ++i)
#pragma unroll
            for (int p = 0; p < 4; ++p) acc[i][p] = 0ull;

        const float zxi = xi, zxf = xf, zxg = xg, zxo = xo;
        if (s + 1 < SLEN) {    // prefetch next xp under compute
            size_t nb = (size_t)(s + 1) * G4 * 64;
            xi = g_xp[nb + (size_t)(0 * HID + j) * 64 + gb];
            xf = g_xp[nb + (size_t)(1 * HID + j) * 64 + gb];
            xg = g_xp[nb + (size_t)(2 * HID + j) * 64 + gb];
            xo = g_xp[nb + (size_t)(3 * HID + j) * 64 + gb];
        }

        asm volatile("cp.async.wait_group 0;");
        __syncwarp();

#pragma unroll 8
        for (int k = 0; k < 64; ++k) {
            float4 hq = *(const float4*)(hst + k * BPB + bh * 4);
            uint64_t h0 = f2_dup(hq.x), h1 = f2_dup(hq.y);
            uint64_t h2 = f2_dup(hq.z), h3 = f2_dup(hq.w);
            const uint64_t* Wk = W2w + (size_t)k * 32 + rg * 4;
            ulonglong2 wA = *(const ulonglong2*)Wk;        // rp rg*4+0, +1
            ulonglong2 wB = *(const ulonglong2*)(Wk + 2);  // rp rg*4+2, +3
            f2_fma(acc[0][0], h0, wA.x); f2_fma(acc[0][1], h1, wA.x);
            f2_fma(acc[0][2], h2, wA.x); f2_fma(acc[0][3], h3, wA.x);
            f2_fma(acc[1][0], h0, wA.y); f2_fma(acc[1][1], h1, wA.y);
            f2_fma(acc[1][2], h2, wA.y); f2_fma(acc[1][3], h3, wA.y);
            f2_fma(acc[2][0], h0, wB.x); f2_fma(acc[2][1], h1, wB.x);
            f2_fma(acc[2][2], h2, wB.x); f2_fma(acc[2][3], h3, wB.x);
            f2_fma(acc[3][0], h0, wB.y); f2_fma(acc[3][1], h1, wB.y);
            f2_fma(acc[3][2], h2, wB.y); f2_fma(acc[3][3], h3, wB.y);
        }

        // --- partials into OWN staging slot (fully consumed; warp-local WAR fence) ---
        __syncwarp();
        {
            uint64_t* part = (uint64_t*)(hreg + w * 4096);   // [32 rp][16 b] pairs
#pragma unroll
            for (int rpl = 0; rpl < 4; ++rpl) {
#pragma unroll
                for (int bi = 0; bi < 4; bi += 2) {
                    int p = (rg * 4 + rpl) * BPB + bh * 4 + bi;
                    *(ulonglong2*)(part + p) =
                        make_ulonglong2(acc[rpl][bi], acc[rpl][bi + 1]);
                }
            }
        }
        __syncthreads();

        // --- reduce over 8 warps: thread t owns pairs 2t, 2t+1 ---
        {
            const uint64_t* part = (const uint64_t*)hreg;
            ulonglong2 v0 = *(const ulonglong2*)(part + 2 * tid);
            uint64_t e = v0.x, o = v0.y;
#pragma unroll
            for (int ww = 1; ww < 8; ++ww) {
                ulonglong2 v = *(const ulonglong2*)(part + ww * 512 + 2 * tid);
                f2_add(e, v.x);
                f2_add(o, v.y);
            }
            int rp = (2 * tid) >> 4;          // pair-row index 0..31
            int b  = (2 * tid) & 15;          // even
            float2 E = f2_unpack(e), O = f2_unpack(o);
            *(float2*)&zb[(2 * rp) * BPB + b]     = make_float2(E.x, O.x);
            *(float2*)&zb[(2 * rp + 1) * BPB + b] = make_float2(E.y, O.y);
        }
        __syncthreads();

        // --- activation: thread (u, bb) ---
        {
            float z_i = zb[(0 * UPB + u) * BPB + bb] + zxi;
            float z_f = zb[(1 * UPB + u) * BPB + bb] + zxf;
            float z_g = zb[(2 * UPB + u) * BPB + bb] + zxg;
            float z_o = zb[(3 * UPB + u) * BPB + bb] + zxo;
            float ig = 1.f / (1.f + __expf(-z_i));
            float fg = 1.f / (1.f + __expf(-z_f));
            float gt = tanhf(z_g);
            float og = 1.f / (1.f + __expf(-z_o));
            c = fg * c + ig * gt;
            float h = og * tanhf(c);

            g_h[s & 1][bg][j * BPB + bb] = h;   // 64B rows, coalesced
            hbuf[bb * UPB + u] = h;

            if (s == SLEN - 1) {
                const size_t SBH = (size_t)SLEN * BATCH * HID;
                size_t o2 = (size_t)gb * HID + j;
                out[SBH + o2] = h;                          // h_f
                out[SBH + (size_t)BATCH * HID + o2] = c;    // c_f
            }
        }
        __syncthreads();   // h + hbuf complete

        // --- arrive: ONE fire-and-forget release add on the group counter ---
        if (tid == 0) {
            asm volatile("red.add.release.gpu.global.u32 [%0], %1;"
                         :: "l"(cntp), "r"(1u) : "memory");
        }

        // out stores: off the publish path, 16 rows x 4 float4
        if (tid < 64) {
            int row = tid >> 2, q = tid & 3;
            float4 hv = *(const float4*)(hbuf + row * UPB + q * 4);
            *(float4*)(out + ((size_t)s * BATCH + bg * BPB + row) * HID
                             + ug * UPB + q * 4) = hv;
        }

        // --- spin for group completion of this step (hidden behind out stores) ---
        if (s + 1 < SLEN) {
            if (tid == 0) {
                const unsigned tgt = (unsigned)(32 * (s + 1));
                unsigned cur;
                do {
                    asm volatile("ld.acquire.gpu.global.u32 %0, [%1];"
                                 : "=r"(cur) : "l"(cntp) : "memory");
                } while ((int)(cur - tgt) < 0);
            }
            __syncthreads();
        }
    }
}

// ---------------- launch ----------------
extern "C" void kernel_launch(void* const* d_in, const int* in_sizes, int n_in,
                              void* d_out, int out_size) {
    (void)in_sizes; (void)n_in; (void)out_size;
    const float* input  = (const float*)d_in[0];  // (2048, 64, 512)
    const float* h_prev = (const float*)d_in[1];  // (64, 512)
    const float* c_prev = (const float*)d_in[2];  // (64, 512)
    const float* w_ih   = (const float*)d_in[3];  // (2048, 512)
    const float* w_hh   = (const float*)d_in[4];  // (2048, 512)
    const float* b_ih   = (const float*)d_in[5];  // (2048,)
    const float* b_hh   = (const float*)d_in[6];  // (2048,)
    float* out = (float*)d_out;

    cudaFuncSetAttribute(lstm_rec_kernel,
                         cudaFuncAttributeMaxDynamicSharedMemorySize, 168960);

    // 2 launches per call -> ncu -s 5 -c 1 lands on lstm_rec_kernel
    dim3 g1(131072 / 128, 2048 / 128);   // (1024, 16)
    xproj_gemm_kernel<<<g1, 256>>>(input, w_ih, b_ih, b_hh, h_prev);

    lstm_rec_kernel<<<NBLK, TPB, 168960>>>(c_prev, w_hh, out);
}

// round 16
// speedup vs baseline: 1.3279x; 1.0002x over previous
#include <cuda_runtime.h>
#include <cstdint>

#define SLEN 2048
#define BATCH 64
#define HID 512
#define G4 2048
#define NBG 4            // batch groups (independent recurrences)
#define NUG 32           // unit groups
#define NBLK (NBG*NUG)   // 128
#define UPB 16           // units per block
#define BPB 16           // batches per block
#define TPB 256

// ---------------- scratch (device globals) ----------------
static __device__ float g_xp[(size_t)SLEN * G4 * BATCH];   // [s][g][b], 1 GiB
static __device__ float g_h[2][NBG][HID * BPB];            // ping-pong h, [bg][j*16+b]
static __device__ unsigned g_cnt[NBG];                     // monotonic arrival counters

// ---------------- packed f32x2 helpers ----------------
__device__ __forceinline__ uint64_t f2_pack(float x, float y) {
    uint64_t r; uint32_t xu = __float_as_uint(x), yu = __float_as_uint(y);
    asm("mov.b64 %0, {%1, %2};" : "=l"(r) : "r"(xu), "r"(yu));
    return r;
}
__device__ __forceinline__ uint64_t f2_dup(float x) {
    uint64_t r; uint32_t xu = __float_as_uint(x);
    asm("mov.b64 %0, {%1, %1};" : "=l"(r) : "r"(xu));
    return r;
}
__device__ __forceinline__ void f2_fma(uint64_t& d, uint64_t a, uint64_t b) {
    asm("fma.rn.f32x2 %0, %1, %2, %0;" : "+l"(d) : "l"(a), "l"(b));
}
__device__ __forceinline__ void f2_add(uint64_t& d, uint64_t a) {
    asm("add.rn.f32x2 %0, %1, %0;" : "+l"(d) : "l"(a));
}
__device__ __forceinline__ float2 f2_unpack(uint64_t v) {
    uint32_t lo, hi;
    asm("mov.b64 {%0, %1}, %2;" : "=r"(lo), "=r"(hi) : "l"(v));
    return make_float2(__uint_as_float(lo), __uint_as_float(hi));
}

// ---------------- kernel 1: x_proj GEMM (+ folded init) ----------------
__global__ __launch_bounds__(256, 2) void xproj_gemm_kernel(
    const float* __restrict__ A,    // (131072, 512)
    const float* __restrict__ W,    // (2048, 512)
    const float* __restrict__ bi,
    const float* __restrict__ bh,
    const float* __restrict__ h_prev)
{
    __shared__ float Ash[16][132];
    __shared__ float Bsh[16][132];

    const int tid = threadIdx.x;

    // folded init: h_prev -> g_h[1][bg][j*16+b_local]; zero group counters
    if (blockIdx.y == 0 && blockIdx.x < 128) {
        int idx = blockIdx.x * 256 + tid;    // 0..32767
        int j = idx >> 6, b = idx & 63;
        g_h[1][b >> 4][j * BPB + (b & 15)] = h_prev[(size_t)b * HID + j];
        if (blockIdx.x == 0 && tid < NBG) g_cnt[tid] = 0u;
    }

    const int tx = tid & 15;
    const int ty = tid >> 4;
    const int m0 = blockIdx.x * 128;
    const int g0 = blockIdx.y * 128;

    uint64_t acc[8][4];
#pragma unroll
    for (int g = 0; g < 8; ++g)
#pragma unroll
        for (int p = 0; p < 4; ++p) acc[g][p] = 0ull;

    for (int kt = 0; kt < 32; ++kt) {
        const int k0 = kt * 16;
#pragma unroll
        for (int i = 0; i < 2; ++i) {
            int idx = tid + i * 256;
            int r = idx >> 2, c4 = idx & 3;
            float4 va = *(const float4*)(A + (size_t)(m0 + r) * 512 + k0 + c4 * 4);
            Ash[c4 * 4 + 0][r] = va.x; Ash[c4 * 4 + 1][r] = va.y;
            Ash[c4 * 4 + 2][r] = va.z; Ash[c4 * 4 + 3][r] = va.w;
            float4 vb = *(const float4*)(W + (size_t)(g0 + r) * 512 + k0 + c4 * 4);
            Bsh[c4 * 4 + 0][r] = vb.x; Bsh[c4 * 4 + 1][r] = vb.y;
            Bsh[c4 * 4 + 2][r] = vb.z; Bsh[c4 * 4 + 3][r] = vb.w;
        }
        __syncthreads();
#pragma unroll
        for (int kk = 0; kk < 16; ++kk) {
            uint64_t a[4];
            const uint64_t* ap = (const uint64_t*)&Ash[kk][ty * 8];
            a[0] = ap[0]; a[1] = ap[1]; a[2] = ap[2]; a[3] = ap[3];
            float4 q0 = *(const float4*)&Bsh[kk][tx * 8];
            float4 q1 = *(const float4*)&Bsh[kk][tx * 8 + 4];
            float bv[8] = {q0.x, q0.y, q0.z, q0.w, q1.x, q1.y, q1.z, q1.w};
#pragma unroll
            for (int g = 0; g < 8; ++g) {
                uint64_t bd = f2_dup(bv[g]);
                f2_fma(acc[g][0], a[0], bd);
                f2_fma(acc[g][1], a[1], bd);
                f2_fma(acc[g][2], a[2], bd);
                f2_fma(acc[g][3], a[3], bd);
            }
        }
        __syncthreads();
    }

    const int s  = blockIdx.x * 2 + (ty >> 3);
    const int b0 = (ty & 7) * 8;
#pragma unroll
    for (int g = 0; g < 8; ++g) {
        int gg = g0 + tx * 8 + g;
        float bsum = __ldg(bi + gg) + __ldg(bh + gg);
        float2 p0 = f2_unpack(acc[g][0]);
        float2 p1 = f2_unpack(acc[g][1]);
        float2 p2 = f2_unpack(acc[g][2]);
        float2 p3 = f2_unpack(acc[g][3]);
        float4 v0 = make_float4(p0.x + bsum, p0.y + bsum, p1.x + bsum, p1.y + bsum);
        float4 v1 = make_float4(p2.x + bsum, p2.y + bsum, p3.x + bsum, p3.y + bsum);
        float* dst = g_xp + ((size_t)s * G4 + gg) * 64 + b0;
        *(float4*)dst = v0;
        *(float4*)(dst + 4) = v1;
    }
}

// ---------------- kernel 2: persistent recurrent LSTM ----------------
// Batch-split: 128 blocks = (bg in 4) x (ug in 32); block = 16 units x 16 batches
// (64 gate rows). h traffic per block per step: 32KB (vs 128KB in R13) ->
// chip 4MB/step (~650 cyc LTS) instead of 16MB (~2600 cyc).
// Sync (R13 discipline, per group): arrive = ONE red.add.release on g_cnt[bg];
// wait = tid0 polls cnt >= 32*(s+1). 32 pollers/line, 4 disjoint lines.
// Compute: 8 warps x 64-k slices; lane=(rg in 8)x(bh in 4); 16 f32x2 accs.
__global__ __launch_bounds__(TPB, 1) void lstm_rec_kernel(
    const float* __restrict__ c_prev,
    const float* __restrict__ Whh,
    float* __restrict__ out)
{
    extern __shared__ char smp[];
    uint64_t* W2u  = (uint64_t*)smp;              // [512 k][32 rp] row pairs, 128 KB
    char*     hreg = smp + 131072;                // staging 32 KB (per-warp 4 KB); partials alias
    float*    zb   = (float*)(smp + 131072 + 32768);          // [64 rows][16 b], 4 KB
    float*    hbuf = (float*)(smp + 131072 + 32768 + 4096);   // [16 b][16 u], 1 KB

    const int tid  = threadIdx.x;
    const int w    = tid >> 5;       // 8 warps, k-slice [64w, 64w+64)
    const int lane = tid & 31;
    const int rg   = lane >> 2;      // row-pair quad 0..7 (rp = rg*4 .. rg*4+3)
    const int bh   = lane & 3;       // b-quad 0..3
    const int u    = tid >> 4;       // activation: unit 0..15
    const int bb   = tid & 15;       // activation: batch local
    const int bg   = blockIdx.x & 3;
    const int ug   = blockIdx.x >> 2;
    const int j    = ug * UPB + u;
    const int gb   = bg * BPB + bb;  // global batch

    // --- W setup: W2u[k*32+rp] = (Whh[row 2rp][k], Whh[row 2rp+1][k]);
    //     local row r (0..63): gate = r>>4, unit = r&15 ---
    for (int idx = tid; idx < 512 * 32; idx += TPB) {
        int k = idx >> 5, rp = idx & 31;
        int r0 = 2 * rp, r1 = 2 * rp + 1;
        int row0 = (r0 >> 4) * HID + ug * UPB + (r0 & 15);
        int row1 = (r1 >> 4) * HID + ug * UPB + (r1 & 15);
        W2u[idx] = f2_pack(Whh[(size_t)row0 * HID + k], Whh[(size_t)row1 * HID + k]);
    }

    float c  = c_prev[(size_t)gb * HID + j];
    float xi = g_xp[(size_t)(0 * HID + j) * 64 + gb];
    float xf = g_xp[(size_t)(1 * HID + j) * 64 + gb];
    float xg = g_xp[(size_t)(2 * HID + j) * 64 + gb];
    float xo = g_xp[(size_t)(3 * HID + j) * 64 + gb];

    float* hst = (float*)(hreg + w * 4096);       // warp slice [64 k local][16 b]
    uint32_t hst_s = (uint32_t)__cvta_generic_to_shared(hst);
    const uint64_t* W2w = W2u + (size_t)w * 64 * 32;   // warp's global-k W base
    const unsigned* cntp = &g_cnt[bg];

    __syncthreads();   // W2u ready

    for (int s = 0; s < SLEN; ++s) {
        // --- stage warp's 4KB h slice (h[s-1] readiness ensured by prev-iter spin) ---
        const float* hsrc = &g_h[(s + 1) & 1][bg][(size_t)w * 64 * BPB];
#pragma unroll
        for (int i = 0; i < 8; ++i) {
            int flat = i * 32 + lane;              // float4 index, 256 per warp
            asm volatile("cp.async.cg.shared.global [%0], [%1], 16;"
                         :: "r"(hst_s + flat * 16), "l"(hsrc + flat * 4));
        }
        asm volatile("cp.async.commit_group;");

        uint64_t acc[4][4];    // [rpl][bi]
#pragma unroll
        for (int i = 0; i < 4; ++i)
#pragma unroll
            for (int p = 0; p < 4; ++p) acc[i][p] = 0ull;

        const float zxi = xi, zxf = xf, zxg = xg, zxo = xo;
        if (s + 1 < SLEN) {    // prefetch next xp under compute
            size_t nb = (size_t)(s + 1) * G4 * 64;
            xi = g_xp[nb + (size_t)(0 * HID + j) * 64 + gb];
            xf = g_xp[nb + (size_t)(1 * HID + j) * 64 + gb];
            xg = g_xp[nb + (size_t)(2 * HID + j) * 64 + gb];
            xo = g_xp[nb + (size_t)(3 * HID + j) * 64 + gb];
        }

        asm volatile("cp.async.wait_group 0;");
        __syncwarp();

#pragma unroll 8
        for (int k = 0; k < 64; ++k) {
            float4 hq = *(const float4*)(hst + k * BPB + bh * 4);
            uint64_t h0 = f2_dup(hq.x), h1 = f2_dup(hq.y);
            uint64_t h2 = f2_dup(hq.z), h3 = f2_dup(hq.w);
            const uint64_t* Wk = W2w + (size_t)k * 32 + rg * 4;
            ulonglong2 wA = *(const ulonglong2*)Wk;        // rp rg*4+0, +1
            ulonglong2 wB = *(const ulonglong2*)(Wk + 2);  // rp rg*4+2, +3
            f2_fma(acc[0][0], h0, wA.x); f2_fma(acc[0][1], h1, wA.x);
            f2_fma(acc[0][2], h2, wA.x); f2_fma(acc[0][3], h3, wA.x);
            f2_fma(acc[1][0], h0, wA.y); f2_fma(acc[1][1], h1, wA.y);
            f2_fma(acc[1][2], h2, wA.y); f2_fma(acc[1][3], h3, wA.y);
            f2_fma(acc[2][0], h0, wB.x); f2_fma(acc[2][1], h1, wB.x);
            f2_fma(acc[2][2], h2, wB.x); f2_fma(acc[2][3], h3, wB.x);
            f2_fma(acc[3][0], h0, wB.y); f2_fma(acc[3][1], h1, wB.y);
            f2_fma(acc[3][2], h2, wB.y); f2_fma(acc[3][3], h3, wB.y);
        }

        // --- partials into OWN staging slot (fully consumed; warp-local WAR fence) ---
        __syncwarp();
        {
            uint64_t* part = (uint64_t*)(hreg + w * 4096);   // [32 rp][16 b] pairs
#pragma unroll
            for (int rpl = 0; rpl < 4; ++rpl) {
#pragma unroll
                for (int bi = 0; bi < 4; bi += 2) {
                    int p = (rg * 4 + rpl) * BPB + bh * 4 + bi;
                    *(ulonglong2*)(part + p) =
                        make_ulonglong2(acc[rpl][bi], acc[rpl][bi + 1]);
                }
            }
        }
        __syncthreads();

        // --- reduce over 8 warps: thread t owns pairs 2t, 2t+1 ---
        {
            const uint64_t* part = (const uint64_t*)hreg;
            ulonglong2 v0 = *(const ulonglong2*)(part + 2 * tid);
            uint64_t e = v0.x, o = v0.y;
#pragma unroll
            for (int ww = 1; ww < 8; ++ww) {
                ulonglong2 v = *(const ulonglong2*)(part + ww * 512 + 2 * tid);
                f2_add(e, v.x);
                f2_add(o, v.y);
            }
            int rp = (2 * tid) >> 4;          // pair-row index 0..31
            int b  = (2 * tid) & 15;          // even
            float2 E = f2_unpack(e), O = f2_unpack(o);
            *(float2*)&zb[(2 * rp) * BPB + b]     = make_float2(E.x, O.x);
            *(float2*)&zb[(2 * rp + 1) * BPB + b] = make_float2(E.y, O.y);
        }
        __syncthreads();

        // --- activation: thread (u, bb) ---
        {
            float z_i = zb[(0 * UPB + u) * BPB + bb] + zxi;
            float z_f = zb[(1 * UPB + u) * BPB + bb] + zxf;
            float z_g = zb[(2 * UPB + u) * BPB + bb] + zxg;
            float z_o = zb[(3 * UPB + u) * BPB + bb] + zxo;
            float ig = 1.f / (1.f + __expf(-z_i));
            float fg = 1.f / (1.f + __expf(-z_f));
            float gt = tanhf(z_g);
            float og = 1.f / (1.f + __expf(-z_o));
            c = fg * c + ig * gt;
            float h = og * tanhf(c);

            g_h[s & 1][bg][j * BPB + bb] = h;   // 64B rows, coalesced
            hbuf[bb * UPB + u] = h;

            if (s == SLEN - 1) {
                const size_t SBH = (size_t)SLEN * BATCH * HID;
                size_t o2 = (size_t)gb * HID + j;
                out[SBH + o2] = h;                          // h_f
                out[SBH + (size_t)BATCH * HID + o2] = c;    // c_f
            }
        }
        __syncthreads();   // h + hbuf complete

        // --- arrive: ONE fire-and-forget release add on the group counter ---
        if (tid == 0) {
            asm volatile("red.add.release.gpu.global.u32 [%0], %1;"
                         :: "l"(cntp), "r"(1u) : "memory");
        }

        // out stores: off the publish path, 16 rows x 4 float4
        if (tid < 64) {
            int row = tid >> 2, q = tid & 3;
            float4 hv = *(const float4*)(hbuf + row * UPB + q * 4);
            *(float4*)(out + ((size_t)s * BATCH + bg * BPB + row) * HID
                             + ug * UPB + q * 4) = hv;
        }

        // --- spin for group completion of this step (hidden behind out stores) ---
        if (s + 1 < SLEN) {
            if (tid == 0) {
                const unsigned tgt = (unsigned)(32 * (s + 1));
                unsigned cur;
                do {
                    asm volatile("ld.acquire.gpu.global.u32 %0, [%1];"
                                 : "=r"(cur) : "l"(cntp) : "memory");
                } while ((int)(cur - tgt) < 0);
            }
            __syncthreads();
        }
    }
}

// ---------------- launch ----------------
extern "C" void kernel_launch(void* const* d_in, const int* in_sizes, int n_in,
                              void* d_out, int out_size) {
    (void)in_sizes; (void)n_in; (void)out_size;
    const float* input  = (const float*)d_in[0];  // (2048, 64, 512)
    const float* h_prev = (const float*)d_in[1];  // (64, 512)
    const float* c_prev = (const float*)d_in[2];  // (64, 512)
    const float* w_ih   = (const float*)d_in[3];  // (2048, 512)
    const float* w_hh   = (const float*)d_in[4];  // (2048, 512)
    const float* b_ih   = (const float*)d_in[5];  // (2048,)
    const float* b_hh   = (const float*)d_in[6];  // (2048,)
    float* out = (float*)d_out;

    cudaFuncSetAttribute(lstm_rec_kernel,
                         cudaFuncAttributeMaxDynamicSharedMemorySize, 168960);

    // 2 launches per call -> ncu -s 5 -c 1 lands on lstm_rec_kernel
    dim3 g1(131072 / 128, 2048 / 128);   // (1024, 16)
    xproj_gemm_kernel<<<g1, 256>>>(input, w_ih, b_ih, b_hh, h_prev);

    lstm_rec_kernel<<<NBLK, TPB, 168960>>>(c_prev, w_hh, out);
}